// round 3
// baseline (speedup 1.0000x reference)
#include <cuda_runtime.h>

#define TT  1024
#define NB  128
#define VV  35
#define HH  512
#define VS  128
#define KSZ 128
#define G1  2048
#define ML  250

typedef unsigned long long ull;

__device__ float d_vmean[NB*VS];
__device__ float d_inpc[NB*G1];
__device__ float d_toktab[VV*G1];
__device__ float d_h1[2][NB*HH];
__device__ float d_c1[NB*HH];
__device__ float d_h2[2][NB*KSZ];
__device__ float d_c2[NB*KSZ];
__device__ int   d_tok[NB];

__device__ __forceinline__ ull pack2(float x) {
    unsigned r = __float_as_uint(x); ull d;
    asm("mov.b64 %0, {%1, %2};" : "=l"(d) : "r"(r), "r"(r));
    return d;
}
__device__ __forceinline__ void ffma2(ull& c, ull a, ull b) {
    asm("fma.rn.f32x2 %0, %1, %2, %0;" : "+l"(c) : "l"(a), "l"(b));
}
__device__ __forceinline__ float2 unpack2(ull v) {
    unsigned lo, hi;
    asm("mov.b64 {%0, %1}, %2;" : "=r"(lo), "=r"(hi) : "l"(v));
    return make_float2(__uint_as_float(lo), __uint_as_float(hi));
}
__device__ __forceinline__ float sigf(float x) { return 1.0f / (1.0f + expf(-x)); }

__global__ void k_vmean(const float* __restrict__ val) {
    int n = blockIdx.x, v = threadIdx.x;
    const float* p = val + n*VS + v;
    float s = 0.f;
    #pragma unroll 8
    for (int t = 0; t < TT; t++) s += p[(size_t)t*NB*VS];
    d_vmean[n*VS+v] = s * (1.0f/TT);
}

__global__ void k_inpc(const float* __restrict__ Wih1, const float* __restrict__ bih1,
                       const float* __restrict__ bhh1) {
    int n = blockIdx.x;
    __shared__ float vm[VS];
    if (threadIdx.x < VS) vm[threadIdx.x] = d_vmean[n*VS + threadIdx.x];
    __syncthreads();
    for (int j = threadIdx.x; j < G1; j += blockDim.x) {
        const float4* w4 = (const float4*)(Wih1 + (size_t)j*(HH+VS) + HH);
        float s = 0.f;
        #pragma unroll 8
        for (int v = 0; v < VS/4; v++) {
            float4 w = w4[v];
            s += w.x*vm[4*v] + w.y*vm[4*v+1] + w.z*vm[4*v+2] + w.w*vm[4*v+3];
        }
        d_inpc[n*G1 + j] = s + bih1[j] + bhh1[j];
    }
}

__global__ void k_toktab(const float* __restrict__ emb, const float* __restrict__ Wih1) {
    int v = blockIdx.x;
    __shared__ float e[HH];
    for (int k = threadIdx.x; k < HH; k += blockDim.x) e[k] = emb[v*HH + k];
    __syncthreads();
    for (int j = threadIdx.x; j < G1; j += blockDim.x) {
        const float4* w4 = (const float4*)(Wih1 + (size_t)j*(HH+VS));
        float s = 0.f;
        #pragma unroll 8
        for (int k = 0; k < HH/4; k++) {
            float4 w = w4[k];
            s += w.x*e[4*k] + w.y*e[4*k+1] + w.z*e[4*k+2] + w.w*e[4*k+3];
        }
        d_toktab[v*G1 + j] = s;
    }
}

__global__ void k_init() {
    int i = blockIdx.x*blockDim.x + threadIdx.x;
    if (i < NB*HH)  { d_h1[0][i] = 0.f; d_c1[i] = 0.f; }
    if (i < NB*KSZ) { d_h2[0][i] = 0.f; d_c2[i] = 0.f; }
    if (i < NB)     d_tok[i] = 0;
}

// LSTM1: gates = h1 @ Whh1^T + toktab[tok] + inpc. grid(32,4), 256 thr.
// Block tile: 32 n-rows x 64 cols (4 gates x 16 cells, cells bx*16..+16).
__global__ void __launch_bounds__(256) k_lstm1(const float* __restrict__ Whh1, int p) {
    const int m0 = blockIdx.x * 16, n0 = blockIdx.y * 32, tid = threadIdx.x;
    __shared__ __align__(16) float As[32][34];
    __shared__ __align__(16) float Bs[32][66];
    __shared__ float gt[64][33];
    const float* h1in = d_h1[p];
    const int tn = tid & 7;              // n group: covers n = 4*tn..+3
    const int j0 = (tid >> 3) * 2;       // cols j0, j0+1
    ull a00=0, a01=0, a10=0, a11=0;
    const int la_n = tid >> 3, la_k = (tid & 7) * 4;
    const int lb_j = tid >> 2, lb_k = (tid & 3) * 8;
    const int lb_row = (lb_j >> 4) * HH + m0 + (lb_j & 15);

    for (int k0 = 0; k0 < HH; k0 += 32) {
        float4 av  = *(const float4*)(h1in + (size_t)(n0+la_n)*HH + k0 + la_k);
        float4 bv0 = *(const float4*)(Whh1 + (size_t)lb_row*HH + k0 + lb_k);
        float4 bv1 = *(const float4*)(Whh1 + (size_t)lb_row*HH + k0 + lb_k + 4);
        __syncthreads();
        As[la_k+0][la_n]=av.x; As[la_k+1][la_n]=av.y; As[la_k+2][la_n]=av.z; As[la_k+3][la_n]=av.w;
        Bs[lb_k+0][lb_j]=bv0.x; Bs[lb_k+1][lb_j]=bv0.y; Bs[lb_k+2][lb_j]=bv0.z; Bs[lb_k+3][lb_j]=bv0.w;
        Bs[lb_k+4][lb_j]=bv1.x; Bs[lb_k+5][lb_j]=bv1.y; Bs[lb_k+6][lb_j]=bv1.z; Bs[lb_k+7][lb_j]=bv1.w;
        __syncthreads();
        #pragma unroll
        for (int k = 0; k < 32; k++) {
            ull a0 = *(const ull*)&As[k][4*tn];
            ull a1 = *(const ull*)&As[k][4*tn+2];
            ull b0 = pack2(Bs[k][j0]), b1 = pack2(Bs[k][j0+1]);
            ffma2(a00,a0,b0); ffma2(a01,a0,b1); ffma2(a10,a1,b0); ffma2(a11,a1,b1);
        }
    }
    __syncthreads();
    { float2 v;
      v=unpack2(a00); gt[j0  ][4*tn  ]=v.x; gt[j0  ][4*tn+1]=v.y;
      v=unpack2(a10); gt[j0  ][4*tn+2]=v.x; gt[j0  ][4*tn+3]=v.y;
      v=unpack2(a01); gt[j0+1][4*tn  ]=v.x; gt[j0+1][4*tn+1]=v.y;
      v=unpack2(a11); gt[j0+1][4*tn+2]=v.x; gt[j0+1][4*tn+3]=v.y; }
    __syncthreads();
    float* h1out = d_h1[p^1];
    #pragma unroll
    for (int cc = 0; cc < 2; cc++) {
        int c = tid + cc*256;
        int nl = c >> 4, mi = c & 15;
        int gn = n0 + nl, gm = m0 + mi;
        const float* tt = d_toktab + (size_t)d_tok[gn]*G1;
        const float* ic = d_inpc + (size_t)gn*G1;
        float gi = gt[mi   ][nl] + tt[gm]      + ic[gm];
        float gf = gt[16+mi][nl] + tt[HH+gm]   + ic[HH+gm];
        float gg = gt[32+mi][nl] + tt[2*HH+gm] + ic[2*HH+gm];
        float go = gt[48+mi][nl] + tt[3*HH+gm] + ic[3*HH+gm];
        float cp = d_c1[gn*HH + gm];
        float cn = sigf(gf)*cp + sigf(gi)*tanhf(gg);
        d_c1[gn*HH + gm] = cn;
        h1out[gn*HH + gm] = sigf(go)*tanhf(cn);
    }
}

// LSTM2: gates = h1n @ Wih2^T + h2 @ Whh2^T + b. grid(16,4), 256 thr.
// Block tile: 32 n x 32 cols (4 gates x 8 cells, cells bx*8..+8).
__global__ void __launch_bounds__(256) k_lstm2(const float* __restrict__ Wih2,
        const float* __restrict__ Whh2, const float* __restrict__ bih2,
        const float* __restrict__ bhh2, int p) {
    const int m0 = blockIdx.x * 8, n0 = blockIdx.y * 32, tid = threadIdx.x;
    __shared__ __align__(16) float As[32][34];
    __shared__ __align__(16) float Bs[32][34];
    __shared__ float gt[32][34];
    const int tn = tid & 15;          // n pair {2tn, 2tn+1}
    const int j0 = (tid >> 4) * 2;    // cols j0, j0+1
    ull a0acc=0, a1acc=0;
    const int la_n = tid >> 3, la_k = (tid & 7) * 4;
    const int lb_j = tid >> 3, lb_k = (tid & 7) * 4;
    const int lb_row = (lb_j >> 3) * KSZ + m0 + (lb_j & 7);

    const float* A1 = d_h1[p^1];
    for (int k0 = 0; k0 < HH; k0 += 32) {
        float4 av = *(const float4*)(A1 + (size_t)(n0+la_n)*HH + k0 + la_k);
        float4 bv = *(const float4*)(Wih2 + (size_t)lb_row*HH + k0 + lb_k);
        __syncthreads();
        As[la_k+0][la_n]=av.x; As[la_k+1][la_n]=av.y; As[la_k+2][la_n]=av.z; As[la_k+3][la_n]=av.w;
        Bs[lb_k+0][lb_j]=bv.x; Bs[lb_k+1][lb_j]=bv.y; Bs[lb_k+2][lb_j]=bv.z; Bs[lb_k+3][lb_j]=bv.w;
        __syncthreads();
        #pragma unroll
        for (int k = 0; k < 32; k++) {
            ull a = *(const ull*)&As[k][2*tn];
            ffma2(a0acc, a, pack2(Bs[k][j0]));
            ffma2(a1acc, a, pack2(Bs[k][j0+1]));
        }
    }
    const float* A2 = d_h2[p];
    for (int k0 = 0; k0 < KSZ; k0 += 32) {
        float4 av = *(const float4*)(A2 + (size_t)(n0+la_n)*KSZ + k0 + la_k);
        float4 bv = *(const float4*)(Whh2 + (size_t)lb_row*KSZ + k0 + lb_k);
        __syncthreads();
        As[la_k+0][la_n]=av.x; As[la_k+1][la_n]=av.y; As[la_k+2][la_n]=av.z; As[la_k+3][la_n]=av.w;
        Bs[lb_k+0][lb_j]=bv.x; Bs[lb_k+1][lb_j]=bv.y; Bs[lb_k+2][lb_j]=bv.z; Bs[lb_k+3][lb_j]=bv.w;
        __syncthreads();
        #pragma unroll
        for (int k = 0; k < 32; k++) {
            ull a = *(const ull*)&As[k][2*tn];
            ffma2(a0acc, a, pack2(Bs[k][j0]));
            ffma2(a1acc, a, pack2(Bs[k][j0+1]));
        }
    }
    __syncthreads();
    { float2 v;
      v=unpack2(a0acc); gt[j0  ][2*tn]=v.x; gt[j0  ][2*tn+1]=v.y;
      v=unpack2(a1acc); gt[j0+1][2*tn]=v.x; gt[j0+1][2*tn+1]=v.y; }
    __syncthreads();
    float* h2out = d_h2[p^1];
    int nl = tid >> 3, mi = tid & 7;
    int gn = n0 + nl, gm = m0 + mi;
    int ri = gm, rf = KSZ+gm, rg = 2*KSZ+gm, ro = 3*KSZ+gm;
    float gi = gt[mi   ][nl] + bih2[ri] + bhh2[ri];
    float gf = gt[8+mi ][nl] + bih2[rf] + bhh2[rf];
    float gg = gt[16+mi][nl] + bih2[rg] + bhh2[rg];
    float go = gt[24+mi][nl] + bih2[ro] + bhh2[ro];
    float cp = d_c2[gn*KSZ + gm];
    float cn = sigf(gf)*cp + sigf(gi)*tanhf(gg);
    d_c2[gn*KSZ + gm] = cn;
    h2out[gn*KSZ + gm] = sigf(go)*tanhf(cn);
}

// attention + output proj + argmax: one block per batch row.
__global__ void __launch_bounds__(256) k_attn(const float* __restrict__ key,
        const float* __restrict__ val, const int* __restrict__ lens,
        const float* __restrict__ Wout, const float* __restrict__ bout,
        float* __restrict__ out, int step, int p) {
    const int n = blockIdx.x, tid = threadIdx.x, lane = tid & 31, wid = tid >> 5;
    __shared__ __align__(16) float h2s[KSZ];
    __shared__ float ctxs[VS];
    __shared__ float ev[TT];
    __shared__ float red[8], red2[8];
    __shared__ float cpart[2][VS];
    __shared__ float preds[VV];

    const float* h2 = d_h2[p^1] + (size_t)n*KSZ;
    if (tid < KSZ) h2s[tid] = h2[tid];
    __syncthreads();
    const int L = lens[n];

    float4 hv = *(const float4*)&h2s[lane*4];
    float wmax = -3.0e38f;
    for (int t = wid; t < L; t += 8) {
        const float4 kv = *(const float4*)(key + (size_t)t*(NB*KSZ) + (size_t)n*KSZ + lane*4);
        float s = kv.x*hv.x + kv.y*hv.y + kv.z*hv.z + kv.w*hv.w;
        s += __shfl_xor_sync(~0u, s, 16); s += __shfl_xor_sync(~0u, s, 8);
        s += __shfl_xor_sync(~0u, s, 4);  s += __shfl_xor_sync(~0u, s, 2);
        s += __shfl_xor_sync(~0u, s, 1);
        if (lane == 0) { ev[t] = s; wmax = fmaxf(wmax, s); }
    }
    if (lane == 0) red[wid] = wmax;
    __syncthreads();
    float m = red[0];
    #pragma unroll
    for (int w = 1; w < 8; w++) m = fmaxf(m, red[w]);

    float psum = 0.f;
    for (int t = tid; t < L; t += 256) { float w = expf(ev[t] - m); ev[t] = w; psum += w; }
    psum += __shfl_xor_sync(~0u, psum, 16); psum += __shfl_xor_sync(~0u, psum, 8);
    psum += __shfl_xor_sync(~0u, psum, 4);  psum += __shfl_xor_sync(~0u, psum, 2);
    psum += __shfl_xor_sync(~0u, psum, 1);
    if (lane == 0) red2[wid] = psum;
    __syncthreads();
    float tot = 0.f;
    #pragma unroll
    for (int w = 0; w < 8; w++) tot += red2[w];
    float inv = 1.0f / tot;
    for (int t = tid; t < L; t += 256) ev[t] *= inv;
    __syncthreads();

    // ctx
    {
        int c = tid & 127, g = tid >> 7;
        float s = 0.f;
        for (int t = g; t < L; t += 2)
            s += ev[t] * val[(size_t)t*(NB*VS) + (size_t)n*VS + c];
        cpart[g][c] = s;
    }
    __syncthreads();
    if (tid < VS) ctxs[tid] = cpart[0][tid] + cpart[1][tid];
    __syncthreads();

    // pred = [h2, ctx] @ Wout^T + b
    for (int v = wid; v < VV; v += 8) {
        const float* wr = Wout + (size_t)v*(KSZ+VS);
        float s = 0.f;
        #pragma unroll
        for (int kk = 0; kk < 8; kk++) {
            int k = lane + kk*32;
            float x = (k < KSZ) ? h2s[k] : ctxs[k-KSZ];
            s += x * wr[k];
        }
        s += __shfl_xor_sync(~0u, s, 16); s += __shfl_xor_sync(~0u, s, 8);
        s += __shfl_xor_sync(~0u, s, 4);  s += __shfl_xor_sync(~0u, s, 2);
        s += __shfl_xor_sync(~0u, s, 1);
        if (lane == 0) preds[v] = s + bout[v];
    }
    __syncthreads();
    if (tid < VV) out[(size_t)n*ML*VV + (size_t)step*VV + tid] = preds[tid];
    if (tid == 0) {
        float best = preds[0]; int bi = 0;
        #pragma unroll
        for (int v = 1; v < VV; v++) if (preds[v] > best) { best = preds[v]; bi = v; }
        d_tok[n] = bi;
    }
}

extern "C" void kernel_launch(void* const* d_in, const int* in_sizes, int n_in,
                              void* d_out, int out_size) {
    const float* key  = (const float*)d_in[0];
    const float* val  = (const float*)d_in[1];
    const int*   lens = (const int*)  d_in[2];
    const float* emb  = (const float*)d_in[3];
    const float* Wih1 = (const float*)d_in[4];
    const float* Whh1 = (const float*)d_in[5];
    const float* bih1 = (const float*)d_in[6];
    const float* bhh1 = (const float*)d_in[7];
    const float* Wih2 = (const float*)d_in[8];
    const float* Whh2 = (const float*)d_in[9];
    const float* bih2 = (const float*)d_in[10];
    const float* bhh2 = (const float*)d_in[11];
    const float* Wout = (const float*)d_in[12];
    const float* bout = (const float*)d_in[13];
    float* out = (float*)d_out;

    k_vmean<<<NB, VS>>>(val);
    k_toktab<<<VV, 256>>>(emb, Wih1);
    k_inpc<<<NB, 256>>>(Wih1, bih1, bhh1);
    k_init<<<(NB*HH + 255)/256, 256>>>();

    for (int step = 0; step < ML; step++) {
        int p = step & 1;
        k_lstm1<<<dim3(32,4), 256>>>(Whh1, p);
        k_lstm2<<<dim3(16,4), 256>>>(Wih2, Whh2, bih2, bhh2, p);
        k_attn<<<NB, 256>>>(key, val, lens, Wout, bout, out, step, p);
    }
}

// round 4
// speedup vs baseline: 2.0711x; 2.0711x over previous
#include <cuda_runtime.h>

#define TT  1024
#define NB  128
#define VV  35
#define HH  512
#define VS  128
#define KSZ 128
#define G1  2048
#define ML  250

typedef unsigned long long ull;

__device__ float d_vmean[NB*VS];
__device__ float d_inpc[NB*G1];
__device__ float d_toktab[VV*G1];
__device__ float d_h1[2][NB*HH];
__device__ float d_c1[NB*HH];
__device__ float d_h2[2][NB*KSZ];
__device__ float d_c2[NB*KSZ];
__device__ int   d_tok[NB];

__device__ __forceinline__ ull pack2(float x) {
    unsigned r = __float_as_uint(x); ull d;
    asm("mov.b64 %0, {%1, %2};" : "=l"(d) : "r"(r), "r"(r));
    return d;
}
__device__ __forceinline__ void ffma2(ull& c, ull a, ull b) {
    asm("fma.rn.f32x2 %0, %1, %2, %0;" : "+l"(c) : "l"(a), "l"(b));
}
__device__ __forceinline__ float2 unpack2(ull v) {
    unsigned lo, hi;
    asm("mov.b64 {%0, %1}, %2;" : "=r"(lo), "=r"(hi) : "l"(v));
    return make_float2(__uint_as_float(lo), __uint_as_float(hi));
}
__device__ __forceinline__ float sigf(float x) { return 1.0f / (1.0f + expf(-x)); }

__global__ void k_vmean(const float* __restrict__ val) {
    int n = blockIdx.x, v = threadIdx.x;
    const float* p = val + n*VS + v;
    float s = 0.f;
    #pragma unroll 8
    for (int t = 0; t < TT; t++) s += p[(size_t)t*NB*VS];
    d_vmean[n*VS+v] = s * (1.0f/TT);
}

__global__ void k_inpc(const float* __restrict__ Wih1, const float* __restrict__ bih1,
                       const float* __restrict__ bhh1) {
    int n = blockIdx.x;
    __shared__ float vm[VS];
    if (threadIdx.x < VS) vm[threadIdx.x] = d_vmean[n*VS + threadIdx.x];
    __syncthreads();
    for (int j = threadIdx.x; j < G1; j += blockDim.x) {
        const float4* w4 = (const float4*)(Wih1 + (size_t)j*(HH+VS) + HH);
        float s = 0.f;
        #pragma unroll 8
        for (int v = 0; v < VS/4; v++) {
            float4 w = w4[v];
            s += w.x*vm[4*v] + w.y*vm[4*v+1] + w.z*vm[4*v+2] + w.w*vm[4*v+3];
        }
        d_inpc[n*G1 + j] = s + bih1[j] + bhh1[j];
    }
}

__global__ void k_toktab(const float* __restrict__ emb, const float* __restrict__ Wih1) {
    int v = blockIdx.x;
    __shared__ float e[HH];
    for (int k = threadIdx.x; k < HH; k += blockDim.x) e[k] = emb[v*HH + k];
    __syncthreads();
    for (int j = threadIdx.x; j < G1; j += blockDim.x) {
        const float4* w4 = (const float4*)(Wih1 + (size_t)j*(HH+VS));
        float s = 0.f;
        #pragma unroll 8
        for (int k = 0; k < HH/4; k++) {
            float4 w = w4[k];
            s += w.x*e[4*k] + w.y*e[4*k+1] + w.z*e[4*k+2] + w.w*e[4*k+3];
        }
        d_toktab[v*G1 + j] = s;
    }
}

__global__ void k_init() {
    int i = blockIdx.x*blockDim.x + threadIdx.x;
    if (i < NB*HH)  { d_h1[0][i] = 0.f; d_c1[i] = 0.f; }
    if (i < NB*KSZ) { d_h2[0][i] = 0.f; d_c2[i] = 0.f; }
    if (i < NB)     d_tok[i] = 0;
}

// LSTM1: gates = h1 @ Whh1^T + toktab[tok] + inpc. grid(32,4), 256 thr.
__global__ void __launch_bounds__(256) k_lstm1(const float* __restrict__ Whh1, int p) {
    const int m0 = blockIdx.x * 16, n0 = blockIdx.y * 32, tid = threadIdx.x;
    __shared__ __align__(16) float As[32][34];
    __shared__ __align__(16) float Bs[32][66];
    __shared__ float gt[64][33];
    const float* h1in = d_h1[p];
    const int tn = tid & 7;
    const int j0 = (tid >> 3) * 2;
    ull a00=0, a01=0, a10=0, a11=0;
    const int la_n = tid >> 3, la_k = (tid & 7) * 4;
    const int lb_j = tid >> 2, lb_k = (tid & 3) * 8;
    const int lb_row = (lb_j >> 4) * HH + m0 + (lb_j & 15);

    for (int k0 = 0; k0 < HH; k0 += 32) {
        float4 av  = *(const float4*)(h1in + (size_t)(n0+la_n)*HH + k0 + la_k);
        float4 bv0 = *(const float4*)(Whh1 + (size_t)lb_row*HH + k0 + lb_k);
        float4 bv1 = *(const float4*)(Whh1 + (size_t)lb_row*HH + k0 + lb_k + 4);
        __syncthreads();
        As[la_k+0][la_n]=av.x; As[la_k+1][la_n]=av.y; As[la_k+2][la_n]=av.z; As[la_k+3][la_n]=av.w;
        Bs[lb_k+0][lb_j]=bv0.x; Bs[lb_k+1][lb_j]=bv0.y; Bs[lb_k+2][lb_j]=bv0.z; Bs[lb_k+3][lb_j]=bv0.w;
        Bs[lb_k+4][lb_j]=bv1.x; Bs[lb_k+5][lb_j]=bv1.y; Bs[lb_k+6][lb_j]=bv1.z; Bs[lb_k+7][lb_j]=bv1.w;
        __syncthreads();
        #pragma unroll
        for (int k = 0; k < 32; k++) {
            ull a0 = *(const ull*)&As[k][4*tn];
            ull a1 = *(const ull*)&As[k][4*tn+2];
            ull b0 = pack2(Bs[k][j0]), b1 = pack2(Bs[k][j0+1]);
            ffma2(a00,a0,b0); ffma2(a01,a0,b1); ffma2(a10,a1,b0); ffma2(a11,a1,b1);
        }
    }
    __syncthreads();
    { float2 v;
      v=unpack2(a00); gt[j0  ][4*tn  ]=v.x; gt[j0  ][4*tn+1]=v.y;
      v=unpack2(a10); gt[j0  ][4*tn+2]=v.x; gt[j0  ][4*tn+3]=v.y;
      v=unpack2(a01); gt[j0+1][4*tn  ]=v.x; gt[j0+1][4*tn+1]=v.y;
      v=unpack2(a11); gt[j0+1][4*tn+2]=v.x; gt[j0+1][4*tn+3]=v.y; }
    __syncthreads();
    float* h1out = d_h1[p^1];
    #pragma unroll
    for (int cc = 0; cc < 2; cc++) {
        int c = tid + cc*256;
        int nl = c >> 4, mi = c & 15;
        int gn = n0 + nl, gm = m0 + mi;
        const float* tt = d_toktab + (size_t)d_tok[gn]*G1;
        const float* ic = d_inpc + (size_t)gn*G1;
        float gi = gt[mi   ][nl] + tt[gm]      + ic[gm];
        float gf = gt[16+mi][nl] + tt[HH+gm]   + ic[HH+gm];
        float gg = gt[32+mi][nl] + tt[2*HH+gm] + ic[2*HH+gm];
        float go = gt[48+mi][nl] + tt[3*HH+gm] + ic[3*HH+gm];
        float cp = d_c1[gn*HH + gm];
        float cn = sigf(gf)*cp + sigf(gi)*tanhf(gg);
        d_c1[gn*HH + gm] = cn;
        h1out[gn*HH + gm] = sigf(go)*tanhf(cn);
    }
}

// LSTM2: gates = h1n @ Wih2^T + h2 @ Whh2^T + b. grid(16,4), 256 thr.
__global__ void __launch_bounds__(256) k_lstm2(const float* __restrict__ Wih2,
        const float* __restrict__ Whh2, const float* __restrict__ bih2,
        const float* __restrict__ bhh2, int p) {
    const int m0 = blockIdx.x * 8, n0 = blockIdx.y * 32, tid = threadIdx.x;
    __shared__ __align__(16) float As[32][34];
    __shared__ __align__(16) float Bs[32][34];
    __shared__ float gt[32][34];
    const int tn = tid & 15;
    const int j0 = (tid >> 4) * 2;
    ull a0acc=0, a1acc=0;
    const int la_n = tid >> 3, la_k = (tid & 7) * 4;
    const int lb_j = tid >> 3, lb_k = (tid & 7) * 4;
    const int lb_row = (lb_j >> 3) * KSZ + m0 + (lb_j & 7);

    const float* A1 = d_h1[p^1];
    for (int k0 = 0; k0 < HH; k0 += 32) {
        float4 av = *(const float4*)(A1 + (size_t)(n0+la_n)*HH + k0 + la_k);
        float4 bv = *(const float4*)(Wih2 + (size_t)lb_row*HH + k0 + lb_k);
        __syncthreads();
        As[la_k+0][la_n]=av.x; As[la_k+1][la_n]=av.y; As[la_k+2][la_n]=av.z; As[la_k+3][la_n]=av.w;
        Bs[lb_k+0][lb_j]=bv.x; Bs[lb_k+1][lb_j]=bv.y; Bs[lb_k+2][lb_j]=bv.z; Bs[lb_k+3][lb_j]=bv.w;
        __syncthreads();
        #pragma unroll
        for (int k = 0; k < 32; k++) {
            ull a = *(const ull*)&As[k][2*tn];
            ffma2(a0acc, a, pack2(Bs[k][j0]));
            ffma2(a1acc, a, pack2(Bs[k][j0+1]));
        }
    }
    const float* A2 = d_h2[p];
    for (int k0 = 0; k0 < KSZ; k0 += 32) {
        float4 av = *(const float4*)(A2 + (size_t)(n0+la_n)*KSZ + k0 + la_k);
        float4 bv = *(const float4*)(Whh2 + (size_t)lb_row*KSZ + k0 + lb_k);
        __syncthreads();
        As[la_k+0][la_n]=av.x; As[la_k+1][la_n]=av.y; As[la_k+2][la_n]=av.z; As[la_k+3][la_n]=av.w;
        Bs[lb_k+0][lb_j]=bv.x; Bs[lb_k+1][lb_j]=bv.y; Bs[lb_k+2][lb_j]=bv.z; Bs[lb_k+3][lb_j]=bv.w;
        __syncthreads();
        #pragma unroll
        for (int k = 0; k < 32; k++) {
            ull a = *(const ull*)&As[k][2*tn];
            ffma2(a0acc, a, pack2(Bs[k][j0]));
            ffma2(a1acc, a, pack2(Bs[k][j0+1]));
        }
    }
    __syncthreads();
    { float2 v;
      v=unpack2(a0acc); gt[j0  ][2*tn]=v.x; gt[j0  ][2*tn+1]=v.y;
      v=unpack2(a1acc); gt[j0+1][2*tn]=v.x; gt[j0+1][2*tn+1]=v.y; }
    __syncthreads();
    float* h2out = d_h2[p^1];
    int nl = tid >> 3, mi = tid & 7;
    int gn = n0 + nl, gm = m0 + mi;
    int ri = gm, rf = KSZ+gm, rg = 2*KSZ+gm, ro = 3*KSZ+gm;
    float gi = gt[mi   ][nl] + bih2[ri] + bhh2[ri];
    float gf = gt[8+mi ][nl] + bih2[rf] + bhh2[rf];
    float gg = gt[16+mi][nl] + bih2[rg] + bhh2[rg];
    float go = gt[24+mi][nl] + bih2[ro] + bhh2[ro];
    float cp = d_c2[gn*KSZ + gm];
    float cn = sigf(gf)*cp + sigf(gi)*tanhf(gg);
    d_c2[gn*KSZ + gm] = cn;
    h2out[gn*KSZ + gm] = sigf(go)*tanhf(cn);
}

// attention + output proj + argmax: one block per batch row, 512 threads.
// Energy & ctx loops are unrolled 4x with independent accumulators (MLP).
__global__ void __launch_bounds__(512) k_attn(const float* __restrict__ key,
        const float* __restrict__ val, const int* __restrict__ lens,
        const float* __restrict__ Wout, const float* __restrict__ bout,
        float* __restrict__ out, int step, int p) {
    const int n = blockIdx.x, tid = threadIdx.x, lane = tid & 31, wid = tid >> 5; // 16 warps
    __shared__ __align__(16) float h2s[KSZ];
    __shared__ float ev[TT];
    __shared__ float red[16], red2[16];
    __shared__ __align__(16) float cpart[16][VS];
    __shared__ float ctxs[VS];
    __shared__ float preds[VV];

    const float* h2 = d_h2[p^1] + (size_t)n*KSZ;
    if (tid < KSZ) h2s[tid] = h2[tid];
    __syncthreads();
    const int L = lens[n];
    const float* krow = key + (size_t)n*KSZ + (size_t)lane*4;
    const float* vrow = val + (size_t)n*VS + (size_t)lane*4;

    // ---- energy: warp per t (stride 16), unroll 4 ----
    float4 hv = *(const float4*)&h2s[lane*4];
    float wmax = -3.0e38f;
    int t = wid;
    for (; t + 48 < L; t += 64) {
        float4 k0 = *(const float4*)(krow + (size_t)(t     )*(NB*KSZ));
        float4 k1 = *(const float4*)(krow + (size_t)(t + 16)*(NB*KSZ));
        float4 k2 = *(const float4*)(krow + (size_t)(t + 32)*(NB*KSZ));
        float4 k3 = *(const float4*)(krow + (size_t)(t + 48)*(NB*KSZ));
        float s0 = k0.x*hv.x + k0.y*hv.y + k0.z*hv.z + k0.w*hv.w;
        float s1 = k1.x*hv.x + k1.y*hv.y + k1.z*hv.z + k1.w*hv.w;
        float s2 = k2.x*hv.x + k2.y*hv.y + k2.z*hv.z + k2.w*hv.w;
        float s3 = k3.x*hv.x + k3.y*hv.y + k3.z*hv.z + k3.w*hv.w;
        #pragma unroll
        for (int sh = 16; sh; sh >>= 1) {
            s0 += __shfl_xor_sync(~0u, s0, sh);
            s1 += __shfl_xor_sync(~0u, s1, sh);
            s2 += __shfl_xor_sync(~0u, s2, sh);
            s3 += __shfl_xor_sync(~0u, s3, sh);
        }
        if (lane == 0) { ev[t]=s0; ev[t+16]=s1; ev[t+32]=s2; ev[t+48]=s3; }
        wmax = fmaxf(wmax, fmaxf(fmaxf(s0,s1), fmaxf(s2,s3)));
    }
    for (; t < L; t += 16) {
        float4 k0 = *(const float4*)(krow + (size_t)t*(NB*KSZ));
        float s0 = k0.x*hv.x + k0.y*hv.y + k0.z*hv.z + k0.w*hv.w;
        #pragma unroll
        for (int sh = 16; sh; sh >>= 1) s0 += __shfl_xor_sync(~0u, s0, sh);
        if (lane == 0) ev[t] = s0;
        wmax = fmaxf(wmax, s0);
    }
    if (lane == 0) red[wid] = wmax;
    __syncthreads();
    float m = red[0];
    #pragma unroll
    for (int w = 1; w < 16; w++) m = fmaxf(m, red[w]);

    // ---- exp + sum ----
    float psum = 0.f;
    for (int q = tid; q < L; q += 512) { float w = expf(ev[q] - m); ev[q] = w; psum += w; }
    #pragma unroll
    for (int sh = 16; sh; sh >>= 1) psum += __shfl_xor_sync(~0u, psum, sh);
    if (lane == 0) red2[wid] = psum;
    __syncthreads();
    float tot = 0.f;
    #pragma unroll
    for (int w = 0; w < 16; w++) tot += red2[w];
    const float inv = 1.0f / tot;

    // ---- ctx: warp per t (stride 16), float4 over 128 channels, unroll 4 ----
    float4 a0 = {0,0,0,0}, a1 = {0,0,0,0}, a2 = {0,0,0,0}, a3 = {0,0,0,0};
    t = wid;
    for (; t + 48 < L; t += 64) {
        float e0 = ev[t], e1 = ev[t+16], e2 = ev[t+32], e3 = ev[t+48];
        float4 v0 = *(const float4*)(vrow + (size_t)(t     )*(NB*VS));
        float4 v1 = *(const float4*)(vrow + (size_t)(t + 16)*(NB*VS));
        float4 v2 = *(const float4*)(vrow + (size_t)(t + 32)*(NB*VS));
        float4 v3 = *(const float4*)(vrow + (size_t)(t + 48)*(NB*VS));
        a0.x += e0*v0.x; a0.y += e0*v0.y; a0.z += e0*v0.z; a0.w += e0*v0.w;
        a1.x += e1*v1.x; a1.y += e1*v1.y; a1.z += e1*v1.z; a1.w += e1*v1.w;
        a2.x += e2*v2.x; a2.y += e2*v2.y; a2.z += e2*v2.z; a2.w += e2*v2.w;
        a3.x += e3*v3.x; a3.y += e3*v3.y; a3.z += e3*v3.z; a3.w += e3*v3.w;
    }
    for (; t < L; t += 16) {
        float e0 = ev[t];
        float4 v0 = *(const float4*)(vrow + (size_t)t*(NB*VS));
        a0.x += e0*v0.x; a0.y += e0*v0.y; a0.z += e0*v0.z; a0.w += e0*v0.w;
    }
    a0.x += a1.x + a2.x + a3.x; a0.y += a1.y + a2.y + a3.y;
    a0.z += a1.z + a2.z + a3.z; a0.w += a1.w + a2.w + a3.w;
    *(float4*)&cpart[wid][lane*4] = a0;
    __syncthreads();
    if (tid < VS) {
        float s = 0.f;
        #pragma unroll
        for (int w = 0; w < 16; w++) s += cpart[w][tid];
        ctxs[tid] = s * inv;
    }
    __syncthreads();

    // ---- pred = [h2, ctx] @ Wout^T + b ----
    for (int v = wid; v < VV; v += 16) {
        const float* wr = Wout + (size_t)v*(KSZ+VS);
        float s = 0.f;
        #pragma unroll
        for (int kk = 0; kk < 8; kk++) {
            int k = lane + kk*32;
            float x = (k < KSZ) ? h2s[k] : ctxs[k-KSZ];
            s += x * wr[k];
        }
        #pragma unroll
        for (int sh = 16; sh; sh >>= 1) s += __shfl_xor_sync(~0u, s, sh);
        if (lane == 0) preds[v] = s + bout[v];
    }
    __syncthreads();
    if (tid < VV) out[(size_t)n*ML*VV + (size_t)step*VV + tid] = preds[tid];
    if (tid == 0) {
        float best = preds[0]; int bi = 0;
        #pragma unroll
        for (int v = 1; v < VV; v++) if (preds[v] > best) { best = preds[v]; bi = v; }
        d_tok[n] = bi;
    }
}

extern "C" void kernel_launch(void* const* d_in, const int* in_sizes, int n_in,
                              void* d_out, int out_size) {
    const float* key  = (const float*)d_in[0];
    const float* val  = (const float*)d_in[1];
    const int*   lens = (const int*)  d_in[2];
    const float* emb  = (const float*)d_in[3];
    const float* Wih1 = (const float*)d_in[4];
    const float* Whh1 = (const float*)d_in[5];
    const float* bih1 = (const float*)d_in[6];
    const float* bhh1 = (const float*)d_in[7];
    const float* Wih2 = (const float*)d_in[8];
    const float* Whh2 = (const float*)d_in[9];
    const float* bih2 = (const float*)d_in[10];
    const float* bhh2 = (const float*)d_in[11];
    const float* Wout = (const float*)d_in[12];
    const float* bout = (const float*)d_in[13];
    float* out = (float*)d_out;

    k_vmean<<<NB, VS>>>(val);
    k_toktab<<<VV, 256>>>(emb, Wih1);
    k_inpc<<<NB, 256>>>(Wih1, bih1, bhh1);
    k_init<<<(NB*HH + 255)/256, 256>>>();

    for (int step = 0; step < ML; step++) {
        int p = step & 1;
        k_lstm1<<<dim3(32,4), 256>>>(Whh1, p);
        k_lstm2<<<dim3(16,4), 256>>>(Wih2, Whh2, bih2, bhh2, p);
        k_attn<<<NB, 512>>>(key, val, lens, Wout, bout, out, step, p);
    }
}

// round 5
// speedup vs baseline: 2.2988x; 1.1099x over previous
#include <cuda_runtime.h>

#define TT  1024
#define NB  128
#define VV  35
#define HH  512
#define VS  128
#define KSZ 128
#define G1  2048
#define ML  250
#define NBLK 128

typedef unsigned long long ull;

__device__ float d_vmean[NB*VS];
__device__ float d_inpc[NB*G1];
__device__ float d_toktab[VV*G1];
__device__ float d_h1[2][NB*HH];
__device__ float d_c1[NB*HH];
__device__ float d_h2[2][NB*KSZ];
__device__ float d_c2[NB*KSZ];
__device__ int   d_tok[NB];
__device__ unsigned d_barcnt;
__device__ unsigned d_bargen;

__device__ __forceinline__ void ffma2(ull& c, ull a, ull b) {
    asm("fma.rn.f32x2 %0, %1, %2, %0;" : "+l"(c) : "l"(a), "l"(b));
}
__device__ __forceinline__ float2 unpack2(ull v) {
    unsigned lo, hi;
    asm("mov.b64 {%0, %1}, %2;" : "=r"(lo), "=r"(hi) : "l"(v));
    return make_float2(__uint_as_float(lo), __uint_as_float(hi));
}
__device__ __forceinline__ float sigf(float x) { return 1.0f / (1.0f + expf(-x)); }

__device__ __forceinline__ void grid_bar() {
    __threadfence();
    __syncthreads();
    if (threadIdx.x == 0) {
        volatile unsigned* genp = &d_bargen;
        unsigned gen = *genp;
        if (atomicAdd(&d_barcnt, 1u) == NBLK - 1) {
            d_barcnt = 0;
            __threadfence();
            *genp = gen + 1;
        } else {
            while (*genp == gen) { }
        }
        __threadfence();
    }
    __syncthreads();
}

// ---------------- precompute ----------------
__global__ void k_vmean(const float* __restrict__ val) {
    int n = blockIdx.x, v = threadIdx.x;
    const float* p = val + n*VS + v;
    float s = 0.f;
    #pragma unroll 8
    for (int t = 0; t < TT; t++) s += p[(size_t)t*NB*VS];
    d_vmean[n*VS+v] = s * (1.0f/TT);
}

__global__ void k_inpc(const float* __restrict__ Wih1, const float* __restrict__ bih1,
                       const float* __restrict__ bhh1) {
    int n = blockIdx.x;
    __shared__ float vm[VS];
    if (threadIdx.x < VS) vm[threadIdx.x] = d_vmean[n*VS + threadIdx.x];
    __syncthreads();
    for (int j = threadIdx.x; j < G1; j += blockDim.x) {
        const float4* w4 = (const float4*)(Wih1 + (size_t)j*(HH+VS) + HH);
        float s = 0.f;
        #pragma unroll 8
        for (int v = 0; v < VS/4; v++) {
            float4 w = w4[v];
            s += w.x*vm[4*v] + w.y*vm[4*v+1] + w.z*vm[4*v+2] + w.w*vm[4*v+3];
        }
        d_inpc[n*G1 + j] = s + bih1[j] + bhh1[j];
    }
}

__global__ void k_toktab(const float* __restrict__ emb, const float* __restrict__ Wih1) {
    int v = blockIdx.x;
    __shared__ float e[HH];
    for (int k = threadIdx.x; k < HH; k += blockDim.x) e[k] = emb[v*HH + k];
    __syncthreads();
    for (int j = threadIdx.x; j < G1; j += blockDim.x) {
        const float4* w4 = (const float4*)(Wih1 + (size_t)j*(HH+VS));
        float s = 0.f;
        #pragma unroll 8
        for (int k = 0; k < HH/4; k++) {
            float4 w = w4[k];
            s += w.x*e[4*k] + w.y*e[4*k+1] + w.z*e[4*k+2] + w.w*e[4*k+3];
        }
        d_toktab[v*G1 + j] = s;
    }
}

__global__ void k_init() {
    int i = blockIdx.x*blockDim.x + threadIdx.x;
    if (i < NB*HH)  { d_h1[0][i] = 0.f; d_c1[i] = 0.f; }
    if (i < NB*KSZ) { d_h2[0][i] = 0.f; d_c2[i] = 0.f; }
    if (i < NB)     d_tok[i] = 0;
}

// ---------------- fused persistent decoder ----------------
struct SMem {
    union {
        struct {
            float  As[2][32][34];
            float2 Bs[2][32][67];
            float  gt[2][64][33];
        } l1;
        struct {
            float  As[2][32][34];
            float2 Bs[2][32][34];
            float  gt[2][32][33];
        } l2;
        struct {
            float ev[TT];
            float cpart[16][VS];
            float h2s[KSZ];
            float ctxs[VS];
            float preds[VV];
            float red[16], red2[16];
        } at;
    } u;
};

__global__ void __launch_bounds__(512, 1) k_decode(
    const float* __restrict__ key, const float* __restrict__ val,
    const int* __restrict__ lens, const float* __restrict__ Whh1,
    const float* __restrict__ Wih2, const float* __restrict__ Whh2,
    const float* __restrict__ bih2, const float* __restrict__ bhh2,
    const float* __restrict__ Wout, const float* __restrict__ bout,
    float* __restrict__ out)
{
    extern __shared__ __align__(16) char smraw[];
    SMem* sm = (SMem*)smraw;
    const int bid = blockIdx.x;
    const int tid = threadIdx.x;
    const int t   = tid & 255, g = tid >> 8;
    const int lane = tid & 31, wid = tid >> 5;

    // lstm1 tile mapping: 128 blocks = (32,4); tile 32n x 64cols
    const int l1_m0 = (bid & 31) * 16, l1_n0 = (bid >> 5) * 32;
    const int l1_tn = t & 7, l1_j0 = (t >> 3) * 2;
    const int l1_la_n = t >> 3, l1_la_k = (t & 7) * 4;
    const int l1_lb_j = t >> 2, l1_lb_k = (t & 3) * 8;
    const int l1_lb_row = (l1_lb_j >> 4) * HH + l1_m0 + (l1_lb_j & 15);

    // lstm2 tile mapping: blocks 0..63 = (16,4); tile 32n x 32cols
    const int l2_m0 = (bid & 15) * 8, l2_n0 = (bid >> 4) * 32;
    const int l2_tn = t & 15, l2_j0 = (t >> 4) * 2;
    const int l2_la_n = t >> 3, l2_la_k = (t & 7) * 4;
    const int l2_lb_j = t >> 3, l2_lb_k = (t & 7) * 4;
    const int l2_lb_row = (l2_lb_j >> 3) * KSZ + l2_m0 + (l2_lb_j & 7);

    for (int step = 0; step < ML; step++) {
        const int p = step & 1;

        // ======== phase 1: LSTM1 (all 128 blocks) ========
        {
            const float* h1in = d_h1[p];
            const float* aptr = h1in + (size_t)(l1_n0 + l1_la_n)*HH + g*256 + l1_la_k;
            const float* bptr = Whh1 + (size_t)l1_lb_row*HH + g*256 + l1_lb_k;
            float4 av  = __ldcg((const float4*)aptr);
            float4 bv0 = *(const float4*)bptr;
            float4 bv1 = *(const float4*)(bptr + 4);
            ull a00=0, a01=0, a10=0, a11=0;
            for (int it = 0; it < 8; it++) {
                __syncthreads();
                sm->u.l1.As[g][l1_la_k+0][l1_la_n] = av.x;
                sm->u.l1.As[g][l1_la_k+1][l1_la_n] = av.y;
                sm->u.l1.As[g][l1_la_k+2][l1_la_n] = av.z;
                sm->u.l1.As[g][l1_la_k+3][l1_la_n] = av.w;
                sm->u.l1.Bs[g][l1_lb_k+0][l1_lb_j] = make_float2(bv0.x, bv0.x);
                sm->u.l1.Bs[g][l1_lb_k+1][l1_lb_j] = make_float2(bv0.y, bv0.y);
                sm->u.l1.Bs[g][l1_lb_k+2][l1_lb_j] = make_float2(bv0.z, bv0.z);
                sm->u.l1.Bs[g][l1_lb_k+3][l1_lb_j] = make_float2(bv0.w, bv0.w);
                sm->u.l1.Bs[g][l1_lb_k+4][l1_lb_j] = make_float2(bv1.x, bv1.x);
                sm->u.l1.Bs[g][l1_lb_k+5][l1_lb_j] = make_float2(bv1.y, bv1.y);
                sm->u.l1.Bs[g][l1_lb_k+6][l1_lb_j] = make_float2(bv1.z, bv1.z);
                sm->u.l1.Bs[g][l1_lb_k+7][l1_lb_j] = make_float2(bv1.w, bv1.w);
                __syncthreads();
                if (it < 7) {
                    av  = __ldcg((const float4*)(aptr + (it+1)*32));
                    bv0 = *(const float4*)(bptr + (it+1)*32);
                    bv1 = *(const float4*)(bptr + (it+1)*32 + 4);
                }
                #pragma unroll
                for (int k = 0; k < 32; k++) {
                    ull a0 = *(const ull*)&sm->u.l1.As[g][k][4*l1_tn];
                    ull a1 = *(const ull*)&sm->u.l1.As[g][k][4*l1_tn+2];
                    ull b0 = *(const ull*)&sm->u.l1.Bs[g][k][l1_j0];
                    ull b1 = *(const ull*)&sm->u.l1.Bs[g][k][l1_j0+1];
                    ffma2(a00,a0,b0); ffma2(a01,a0,b1);
                    ffma2(a10,a1,b0); ffma2(a11,a1,b1);
                }
            }
            __syncthreads();
            { float2 v;
              v=unpack2(a00); sm->u.l1.gt[g][l1_j0  ][4*l1_tn  ]=v.x; sm->u.l1.gt[g][l1_j0  ][4*l1_tn+1]=v.y;
              v=unpack2(a10); sm->u.l1.gt[g][l1_j0  ][4*l1_tn+2]=v.x; sm->u.l1.gt[g][l1_j0  ][4*l1_tn+3]=v.y;
              v=unpack2(a01); sm->u.l1.gt[g][l1_j0+1][4*l1_tn  ]=v.x; sm->u.l1.gt[g][l1_j0+1][4*l1_tn+1]=v.y;
              v=unpack2(a11); sm->u.l1.gt[g][l1_j0+1][4*l1_tn+2]=v.x; sm->u.l1.gt[g][l1_j0+1][4*l1_tn+3]=v.y; }
            __syncthreads();
            // epilogue: 512 threads, one cell each (32n x 16m)
            int nl = tid >> 4, mi = tid & 15;
            int gn = l1_n0 + nl, gm = l1_m0 + mi;
            int tk = __ldcg(&d_tok[gn]);
            const float* tt = d_toktab + (size_t)tk*G1;
            const float* ic = d_inpc + (size_t)gn*G1;
            float gi = sm->u.l1.gt[0][mi   ][nl] + sm->u.l1.gt[1][mi   ][nl] + tt[gm]      + ic[gm];
            float gf = sm->u.l1.gt[0][16+mi][nl] + sm->u.l1.gt[1][16+mi][nl] + tt[HH+gm]   + ic[HH+gm];
            float gg = sm->u.l1.gt[0][32+mi][nl] + sm->u.l1.gt[1][32+mi][nl] + tt[2*HH+gm] + ic[2*HH+gm];
            float go = sm->u.l1.gt[0][48+mi][nl] + sm->u.l1.gt[1][48+mi][nl] + tt[3*HH+gm] + ic[3*HH+gm];
            float cp = d_c1[gn*HH + gm];
            float cn = sigf(gf)*cp + sigf(gi)*tanhf(gg);
            d_c1[gn*HH + gm] = cn;
            d_h1[p^1][gn*HH + gm] = sigf(go)*tanhf(cn);
        }
        grid_bar();

        // ======== phase 2: LSTM2 (blocks 0..63) ========
        if (bid < 64) {
            const float* A1 = d_h1[p^1];
            const float* A2 = d_h2[p];
            ull a0acc = 0, a1acc = 0;
            auto ap = [&](int it) -> const float* {
                return (it < 8)
                    ? A1 + (size_t)(l2_n0 + l2_la_n)*HH  + g*256 + it*32      + l2_la_k
                    : A2 + (size_t)(l2_n0 + l2_la_n)*KSZ + g*64  + (it-8)*32  + l2_la_k;
            };
            auto bp = [&](int it) -> const float* {
                return (it < 8)
                    ? Wih2 + (size_t)l2_lb_row*HH  + g*256 + it*32     + l2_lb_k
                    : Whh2 + (size_t)l2_lb_row*KSZ + g*64  + (it-8)*32 + l2_lb_k;
            };
            float4 av = __ldcg((const float4*)ap(0));
            float4 bv = *(const float4*)bp(0);
            for (int it = 0; it < 10; it++) {
                __syncthreads();
                sm->u.l2.As[g][l2_la_k+0][l2_la_n] = av.x;
                sm->u.l2.As[g][l2_la_k+1][l2_la_n] = av.y;
                sm->u.l2.As[g][l2_la_k+2][l2_la_n] = av.z;
                sm->u.l2.As[g][l2_la_k+3][l2_la_n] = av.w;
                sm->u.l2.Bs[g][l2_lb_k+0][l2_lb_j] = make_float2(bv.x, bv.x);
                sm->u.l2.Bs[g][l2_lb_k+1][l2_lb_j] = make_float2(bv.y, bv.y);
                sm->u.l2.Bs[g][l2_lb_k+2][l2_lb_j] = make_float2(bv.z, bv.z);
                sm->u.l2.Bs[g][l2_lb_k+3][l2_lb_j] = make_float2(bv.w, bv.w);
                __syncthreads();
                if (it < 9) {
                    av = __ldcg((const float4*)ap(it+1));
                    bv = *(const float4*)bp(it+1);
                }
                #pragma unroll
                for (int k = 0; k < 32; k++) {
                    ull a  = *(const ull*)&sm->u.l2.As[g][k][2*l2_tn];
                    ull b0 = *(const ull*)&sm->u.l2.Bs[g][k][l2_j0];
                    ull b1 = *(const ull*)&sm->u.l2.Bs[g][k][l2_j0+1];
                    ffma2(a0acc, a, b0);
                    ffma2(a1acc, a, b1);
                }
            }
            __syncthreads();
            { float2 v;
              v=unpack2(a0acc); sm->u.l2.gt[g][l2_j0  ][2*l2_tn]=v.x; sm->u.l2.gt[g][l2_j0  ][2*l2_tn+1]=v.y;
              v=unpack2(a1acc); sm->u.l2.gt[g][l2_j0+1][2*l2_tn]=v.x; sm->u.l2.gt[g][l2_j0+1][2*l2_tn+1]=v.y; }
            __syncthreads();
            if (tid < 256) {
                int nl = tid >> 3, mi = tid & 7;
                int gn = l2_n0 + nl, gm = l2_m0 + mi;
                int ri = gm, rf = KSZ+gm, rg = 2*KSZ+gm, ro = 3*KSZ+gm;
                float gi = sm->u.l2.gt[0][mi   ][nl] + sm->u.l2.gt[1][mi   ][nl] + bih2[ri] + bhh2[ri];
                float gf = sm->u.l2.gt[0][8+mi ][nl] + sm->u.l2.gt[1][8+mi ][nl] + bih2[rf] + bhh2[rf];
                float gg = sm->u.l2.gt[0][16+mi][nl] + sm->u.l2.gt[1][16+mi][nl] + bih2[rg] + bhh2[rg];
                float go = sm->u.l2.gt[0][24+mi][nl] + sm->u.l2.gt[1][24+mi][nl] + bih2[ro] + bhh2[ro];
                float cp = d_c2[gn*KSZ + gm];
                float cn = sigf(gf)*cp + sigf(gi)*tanhf(gg);
                d_c2[gn*KSZ + gm] = cn;
                d_h2[p^1][gn*KSZ + gm] = sigf(go)*tanhf(cn);
            }
        }
        grid_bar();

        // ======== phase 3: attention + output + argmax (block = batch row) ========
        {
            const int n = bid;
            float* ev   = sm->u.at.ev;
            float* h2s  = sm->u.at.h2s;
            float* ctxs = sm->u.at.ctxs;
            float* preds= sm->u.at.preds;
            float* red  = sm->u.at.red;
            float* red2 = sm->u.at.red2;
            if (tid < KSZ) h2s[tid] = __ldcg(&d_h2[p^1][(size_t)n*KSZ + tid]);
            __syncthreads();
            const int L = lens[n];
            const float* krow = key + (size_t)n*KSZ + (size_t)lane*4;
            const float* vrow = val + (size_t)n*VS  + (size_t)lane*4;

            float4 hv = *(const float4*)&h2s[lane*4];
            float wmax = -3.0e38f;
            int tt = wid;
            for (; tt + 48 < L; tt += 64) {
                float4 k0 = *(const float4*)(krow + (size_t)(tt     )*(NB*KSZ));
                float4 k1 = *(const float4*)(krow + (size_t)(tt + 16)*(NB*KSZ));
                float4 k2 = *(const float4*)(krow + (size_t)(tt + 32)*(NB*KSZ));
                float4 k3 = *(const float4*)(krow + (size_t)(tt + 48)*(NB*KSZ));
                float s0 = k0.x*hv.x + k0.y*hv.y + k0.z*hv.z + k0.w*hv.w;
                float s1 = k1.x*hv.x + k1.y*hv.y + k1.z*hv.z + k1.w*hv.w;
                float s2 = k2.x*hv.x + k2.y*hv.y + k2.z*hv.z + k2.w*hv.w;
                float s3 = k3.x*hv.x + k3.y*hv.y + k3.z*hv.z + k3.w*hv.w;
                #pragma unroll
                for (int sh = 16; sh; sh >>= 1) {
                    s0 += __shfl_xor_sync(~0u, s0, sh);
                    s1 += __shfl_xor_sync(~0u, s1, sh);
                    s2 += __shfl_xor_sync(~0u, s2, sh);
                    s3 += __shfl_xor_sync(~0u, s3, sh);
                }
                if (lane == 0) { ev[tt]=s0; ev[tt+16]=s1; ev[tt+32]=s2; ev[tt+48]=s3; }
                wmax = fmaxf(wmax, fmaxf(fmaxf(s0,s1), fmaxf(s2,s3)));
            }
            for (; tt < L; tt += 16) {
                float4 k0 = *(const float4*)(krow + (size_t)tt*(NB*KSZ));
                float s0 = k0.x*hv.x + k0.y*hv.y + k0.z*hv.z + k0.w*hv.w;
                #pragma unroll
                for (int sh = 16; sh; sh >>= 1) s0 += __shfl_xor_sync(~0u, s0, sh);
                if (lane == 0) ev[tt] = s0;
                wmax = fmaxf(wmax, s0);
            }
            if (lane == 0) red[wid] = wmax;
            __syncthreads();
            float m = red[0];
            #pragma unroll
            for (int w = 1; w < 16; w++) m = fmaxf(m, red[w]);

            float psum = 0.f;
            for (int q = tid; q < L; q += 512) { float w = expf(ev[q] - m); ev[q] = w; psum += w; }
            #pragma unroll
            for (int sh = 16; sh; sh >>= 1) psum += __shfl_xor_sync(~0u, psum, sh);
            if (lane == 0) red2[wid] = psum;
            __syncthreads();
            float tot = 0.f;
            #pragma unroll
            for (int w = 0; w < 16; w++) tot += red2[w];
            const float inv = 1.0f / tot;

            float4 a0 = {0,0,0,0}, a1 = {0,0,0,0}, a2 = {0,0,0,0}, a3 = {0,0,0,0};
            tt = wid;
            for (; tt + 48 < L; tt += 64) {
                float e0 = ev[tt], e1 = ev[tt+16], e2 = ev[tt+32], e3 = ev[tt+48];
                float4 v0 = *(const float4*)(vrow + (size_t)(tt     )*(NB*VS));
                float4 v1 = *(const float4*)(vrow + (size_t)(tt + 16)*(NB*VS));
                float4 v2 = *(const float4*)(vrow + (size_t)(tt + 32)*(NB*VS));
                float4 v3 = *(const float4*)(vrow + (size_t)(tt + 48)*(NB*VS));
                a0.x += e0*v0.x; a0.y += e0*v0.y; a0.z += e0*v0.z; a0.w += e0*v0.w;
                a1.x += e1*v1.x; a1.y += e1*v1.y; a1.z += e1*v1.z; a1.w += e1*v1.w;
                a2.x += e2*v2.x; a2.y += e2*v2.y; a2.z += e2*v2.z; a2.w += e2*v2.w;
                a3.x += e3*v3.x; a3.y += e3*v3.y; a3.z += e3*v3.z; a3.w += e3*v3.w;
            }
            for (; tt < L; tt += 16) {
                float e0 = ev[tt];
                float4 v0 = *(const float4*)(vrow + (size_t)tt*(NB*VS));
                a0.x += e0*v0.x; a0.y += e0*v0.y; a0.z += e0*v0.z; a0.w += e0*v0.w;
            }
            a0.x += a1.x + a2.x + a3.x; a0.y += a1.y + a2.y + a3.y;
            a0.z += a1.z + a2.z + a3.z; a0.w += a1.w + a2.w + a3.w;
            *(float4*)&sm->u.at.cpart[wid][lane*4] = a0;
            __syncthreads();
            if (tid < VS) {
                float s = 0.f;
                #pragma unroll
                for (int w = 0; w < 16; w++) s += sm->u.at.cpart[w][tid];
                ctxs[tid] = s * inv;
            }
            __syncthreads();

            for (int v = wid; v < VV; v += 16) {
                const float* wr = Wout + (size_t)v*(KSZ+VS);
                float s = 0.f;
                #pragma unroll
                for (int kk = 0; kk < 8; kk++) {
                    int k = lane + kk*32;
                    float x = (k < KSZ) ? h2s[k] : ctxs[k-KSZ];
                    s += x * wr[k];
                }
                #pragma unroll
                for (int sh = 16; sh; sh >>= 1) s += __shfl_xor_sync(~0u, s, sh);
                if (lane == 0) preds[v] = s + bout[v];
            }
            __syncthreads();
            if (tid < VV) out[(size_t)n*ML*VV + (size_t)step*VV + tid] = preds[tid];
            if (tid == 0) {
                float best = preds[0]; int bi = 0;
                #pragma unroll
                for (int v = 1; v < VV; v++) if (preds[v] > best) { best = preds[v]; bi = v; }
                d_tok[n] = bi;
            }
        }
        grid_bar();
    }
}

extern "C" void kernel_launch(void* const* d_in, const int* in_sizes, int n_in,
                              void* d_out, int out_size) {
    const float* key  = (const float*)d_in[0];
    const float* val  = (const float*)d_in[1];
    const int*   lens = (const int*)  d_in[2];
    const float* emb  = (const float*)d_in[3];
    const float* Wih1 = (const float*)d_in[4];
    const float* Whh1 = (const float*)d_in[5];
    const float* bih1 = (const float*)d_in[6];
    const float* bhh1 = (const float*)d_in[7];
    const float* Wih2 = (const float*)d_in[8];
    const float* Whh2 = (const float*)d_in[9];
    const float* bih2 = (const float*)d_in[10];
    const float* bhh2 = (const float*)d_in[11];
    const float* Wout = (const float*)d_in[12];
    const float* bout = (const float*)d_in[13];
    float* out = (float*)d_out;

    cudaFuncSetAttribute(k_decode, cudaFuncAttributeMaxDynamicSharedMemorySize,
                         (int)sizeof(SMem));

    k_vmean<<<NB, VS>>>(val);
    k_toktab<<<VV, 256>>>(emb, Wih1);
    k_inpc<<<NB, 256>>>(Wih1, bih1, bhh1);
    k_init<<<(NB*HH + 255)/256, 256>>>();
    k_decode<<<NBLK, 512, sizeof(SMem)>>>(key, val, lens, Whh1, Wih2, Whh2,
                                          bih2, bhh2, Wout, bout, out);
}

// round 6
// speedup vs baseline: 2.3649x; 1.0288x over previous
#include <cuda_runtime.h>

#define TT  1024
#define NB  128
#define VV  35
#define HH  512
#define VS  128
#define KSZ 128
#define G1  2048
#define ML  250
#define NBLK 128

typedef unsigned long long ull;

__device__ float d_vmean[NB*VS];
__device__ float d_inpc[NB*G1];
__device__ float d_toktab[VV*G1];
__device__ float d_h1[2][NB*HH];
__device__ float d_c1[NB*HH];
__device__ float d_h2[2][NB*KSZ];
__device__ float d_c2[NB*KSZ];
__device__ int   d_tok[NB];
__device__ unsigned d_barcnt;
__device__ unsigned d_bargen;

__device__ __forceinline__ void ffma2(ull& c, ull a, ull b) {
    asm("fma.rn.f32x2 %0, %1, %2, %0;" : "+l"(c) : "l"(a), "l"(b));
}
__device__ __forceinline__ float2 unpack2(ull v) {
    unsigned lo, hi;
    asm("mov.b64 {%0, %1}, %2;" : "=r"(lo), "=r"(hi) : "l"(v));
    return make_float2(__uint_as_float(lo), __uint_as_float(hi));
}
__device__ __forceinline__ float sigf(float x) { return 1.0f / (1.0f + expf(-x)); }

__device__ __forceinline__ void grid_bar() {
    __threadfence();
    __syncthreads();
    if (threadIdx.x == 0) {
        volatile unsigned* genp = &d_bargen;
        unsigned gen = *genp;
        if (atomicAdd(&d_barcnt, 1u) == NBLK - 1) {
            d_barcnt = 0;
            __threadfence();
            *genp = gen + 1;
        } else {
            while (*genp == gen) { }
        }
        __threadfence();
    }
    __syncthreads();
}

// ---------------- precompute ----------------
__global__ void k_vmean(const float* __restrict__ val) {
    int n = blockIdx.x, v = threadIdx.x;
    const float* p = val + n*VS + v;
    float s = 0.f;
    #pragma unroll 8
    for (int t = 0; t < TT; t++) s += p[(size_t)t*NB*VS];
    d_vmean[n*VS+v] = s * (1.0f/TT);
}

__global__ void k_inpc(const float* __restrict__ Wih1, const float* __restrict__ bih1,
                       const float* __restrict__ bhh1) {
    int n = blockIdx.x;
    __shared__ float vm[VS];
    if (threadIdx.x < VS) vm[threadIdx.x] = d_vmean[n*VS + threadIdx.x];
    __syncthreads();
    for (int j = threadIdx.x; j < G1; j += blockDim.x) {
        const float4* w4 = (const float4*)(Wih1 + (size_t)j*(HH+VS) + HH);
        float s = 0.f;
        #pragma unroll 8
        for (int v = 0; v < VS/4; v++) {
            float4 w = w4[v];
            s += w.x*vm[4*v] + w.y*vm[4*v+1] + w.z*vm[4*v+2] + w.w*vm[4*v+3];
        }
        d_inpc[n*G1 + j] = s + bih1[j] + bhh1[j];
    }
}

__global__ void k_toktab(const float* __restrict__ emb, const float* __restrict__ Wih1) {
    int v = blockIdx.x;
    __shared__ float e[HH];
    for (int k = threadIdx.x; k < HH; k += blockDim.x) e[k] = emb[v*HH + k];
    __syncthreads();
    for (int j = threadIdx.x; j < G1; j += blockDim.x) {
        const float4* w4 = (const float4*)(Wih1 + (size_t)j*(HH+VS));
        float s = 0.f;
        #pragma unroll 8
        for (int k = 0; k < HH/4; k++) {
            float4 w = w4[k];
            s += w.x*e[4*k] + w.y*e[4*k+1] + w.z*e[4*k+2] + w.w*e[4*k+3];
        }
        d_toktab[v*G1 + j] = s;
    }
}

__global__ void k_init() {
    int i = blockIdx.x*blockDim.x + threadIdx.x;
    if (i < NB*HH)  { d_h1[0][i] = 0.f; d_c1[i] = 0.f; }
    if (i < NB*KSZ) { d_h2[0][i] = 0.f; d_c2[i] = 0.f; }
    if (i < NB)     d_tok[i] = 0;
}

// ---------------- fused persistent decoder ----------------
struct SMem {
    union {
        struct {
            float  As[2][32][34];
            float2 Bs[2][32][67];
            float  gt[2][64][33];
        } l1;
        struct {
            float  As[2][32][34];
            float2 Bs[2][32][34];
            float  gt[2][32][33];
        } l2;
        struct {
            float ev[TT];
            float cpart[16][VS];
            float h2s[KSZ];
            float ctxs[VS];
            float preds[VV];
            float red[16], red2[16];
        } at;
    } u;
};

__global__ void __launch_bounds__(512, 1) k_decode(
    const float* __restrict__ key, const float* __restrict__ val,
    const int* __restrict__ lens, const float* __restrict__ Whh1,
    const float* __restrict__ Wih2, const float* __restrict__ Whh2,
    const float* __restrict__ bih2, const float* __restrict__ bhh2,
    const float* __restrict__ Wout, const float* __restrict__ bout,
    float* __restrict__ out)
{
    extern __shared__ __align__(16) char smraw[];
    SMem* sm = (SMem*)smraw;
    const int bid = blockIdx.x;
    const int tid = threadIdx.x;
    const int t   = tid & 255, g = tid >> 8;
    const int lane = tid & 31, wid = tid >> 5;

    // lstm1 tile mapping: 128 blocks = (32,4); tile 32n x 64cols
    const int l1_m0 = (bid & 31) * 16, l1_n0 = (bid >> 5) * 32;
    const int l1_tn = t & 7, l1_j0 = (t >> 3) * 2;
    const int l1_la_n = t >> 3, l1_la_k = (t & 7) * 4;
    const int l1_lb_j = t >> 2, l1_lb_k = (t & 3) * 8;
    const int l1_lb_row = (l1_lb_j >> 4) * HH + l1_m0 + (l1_lb_j & 15);

    // lstm2 tile mapping: blocks 0..63 = (16,4); tile 32n x 32cols
    const int l2_m0 = (bid & 15) * 8, l2_n0 = (bid >> 4) * 32;
    const int l2_tn = t & 15, l2_j0 = (t >> 4) * 2;
    const int l2_la_n = t >> 3, l2_la_k = (t & 7) * 4;
    const int l2_lb_j = t >> 3, l2_lb_k = (t & 7) * 4;
    const int l2_lb_row = (l2_lb_j >> 3) * KSZ + l2_m0 + (l2_lb_j & 7);

    for (int step = 0; step < ML; step++) {
        const int p = step & 1;

        // ======== phase 1: LSTM1 (all 128 blocks) ========
        {
            const float* h1in = d_h1[p];
            const float* aptr = h1in + (size_t)(l1_n0 + l1_la_n)*HH + g*256 + l1_la_k;
            const float* bptr = Whh1 + (size_t)l1_lb_row*HH + g*256 + l1_lb_k;
            float4 av  = __ldcg((const float4*)aptr);
            float4 bv0 = *(const float4*)bptr;
            float4 bv1 = *(const float4*)(bptr + 4);
            ull a00=0, a01=0, a10=0, a11=0;
            for (int it = 0; it < 8; it++) {
                __syncthreads();
                sm->u.l1.As[g][l1_la_k+0][l1_la_n] = av.x;
                sm->u.l1.As[g][l1_la_k+1][l1_la_n] = av.y;
                sm->u.l1.As[g][l1_la_k+2][l1_la_n] = av.z;
                sm->u.l1.As[g][l1_la_k+3][l1_la_n] = av.w;
                sm->u.l1.Bs[g][l1_lb_k+0][l1_lb_j] = make_float2(bv0.x, bv0.x);
                sm->u.l1.Bs[g][l1_lb_k+1][l1_lb_j] = make_float2(bv0.y, bv0.y);
                sm->u.l1.Bs[g][l1_lb_k+2][l1_lb_j] = make_float2(bv0.z, bv0.z);
                sm->u.l1.Bs[g][l1_lb_k+3][l1_lb_j] = make_float2(bv0.w, bv0.w);
                sm->u.l1.Bs[g][l1_lb_k+4][l1_lb_j] = make_float2(bv1.x, bv1.x);
                sm->u.l1.Bs[g][l1_lb_k+5][l1_lb_j] = make_float2(bv1.y, bv1.y);
                sm->u.l1.Bs[g][l1_lb_k+6][l1_lb_j] = make_float2(bv1.z, bv1.z);
                sm->u.l1.Bs[g][l1_lb_k+7][l1_lb_j] = make_float2(bv1.w, bv1.w);
                __syncthreads();
                if (it < 7) {
                    av  = __ldcg((const float4*)(aptr + (it+1)*32));
                    bv0 = *(const float4*)(bptr + (it+1)*32);
                    bv1 = *(const float4*)(bptr + (it+1)*32 + 4);
                }
                #pragma unroll
                for (int k = 0; k < 32; k++) {
                    ull a0 = *(const ull*)&sm->u.l1.As[g][k][4*l1_tn];
                    ull a1 = *(const ull*)&sm->u.l1.As[g][k][4*l1_tn+2];
                    ull b0 = *(const ull*)&sm->u.l1.Bs[g][k][l1_j0];
                    ull b1 = *(const ull*)&sm->u.l1.Bs[g][k][l1_j0+1];
                    ffma2(a00,a0,b0); ffma2(a01,a0,b1);
                    ffma2(a10,a1,b0); ffma2(a11,a1,b1);
                }
            }
            __syncthreads();
            { float2 v;
              v=unpack2(a00); sm->u.l1.gt[g][l1_j0  ][4*l1_tn  ]=v.x; sm->u.l1.gt[g][l1_j0  ][4*l1_tn+1]=v.y;
              v=unpack2(a10); sm->u.l1.gt[g][l1_j0  ][4*l1_tn+2]=v.x; sm->u.l1.gt[g][l1_j0  ][4*l1_tn+3]=v.y;
              v=unpack2(a01); sm->u.l1.gt[g][l1_j0+1][4*l1_tn  ]=v.x; sm->u.l1.gt[g][l1_j0+1][4*l1_tn+1]=v.y;
              v=unpack2(a11); sm->u.l1.gt[g][l1_j0+1][4*l1_tn+2]=v.x; sm->u.l1.gt[g][l1_j0+1][4*l1_tn+3]=v.y; }
            __syncthreads();
            // epilogue: 512 threads, one cell each (32n x 16m)
            int nl = tid >> 4, mi = tid & 15;
            int gn = l1_n0 + nl, gm = l1_m0 + mi;
            int tk = __ldcg(&d_tok[gn]);
            const float* tt = d_toktab + (size_t)tk*G1;
            const float* ic = d_inpc + (size_t)gn*G1;
            float gi = sm->u.l1.gt[0][mi   ][nl] + sm->u.l1.gt[1][mi   ][nl] + tt[gm]      + ic[gm];
            float gf = sm->u.l1.gt[0][16+mi][nl] + sm->u.l1.gt[1][16+mi][nl] + tt[HH+gm]   + ic[HH+gm];
            float gg = sm->u.l1.gt[0][32+mi][nl] + sm->u.l1.gt[1][32+mi][nl] + tt[2*HH+gm] + ic[2*HH+gm];
            float go = sm->u.l1.gt[0][48+mi][nl] + sm->u.l1.gt[1][48+mi][nl] + tt[3*HH+gm] + ic[3*HH+gm];
            float cp = d_c1[gn*HH + gm];
            float cn = sigf(gf)*cp + sigf(gi)*tanhf(gg);
            d_c1[gn*HH + gm] = cn;
            d_h1[p^1][gn*HH + gm] = sigf(go)*tanhf(cn);
        }
        grid_bar();

        // ======== phase 2: LSTM2 (blocks 0..63) ========
        if (bid < 64) {
            const float* A1 = d_h1[p^1];
            const float* A2 = d_h2[p];
            ull a0acc = 0, a1acc = 0;
            auto ap = [&](int it) -> const float* {
                return (it < 8)
                    ? A1 + (size_t)(l2_n0 + l2_la_n)*HH  + g*256 + it*32      + l2_la_k
                    : A2 + (size_t)(l2_n0 + l2_la_n)*KSZ + g*64  + (it-8)*32  + l2_la_k;
            };
            auto bp = [&](int it) -> const float* {
                return (it < 8)
                    ? Wih2 + (size_t)l2_lb_row*HH  + g*256 + it*32     + l2_lb_k
                    : Whh2 + (size_t)l2_lb_row*KSZ + g*64  + (it-8)*32 + l2_lb_k;
            };
            float4 av = __ldcg((const float4*)ap(0));
            float4 bv = *(const float4*)bp(0);
            for (int it = 0; it < 10; it++) {
                __syncthreads();
                sm->u.l2.As[g][l2_la_k+0][l2_la_n] = av.x;
                sm->u.l2.As[g][l2_la_k+1][l2_la_n] = av.y;
                sm->u.l2.As[g][l2_la_k+2][l2_la_n] = av.z;
                sm->u.l2.As[g][l2_la_k+3][l2_la_n] = av.w;
                sm->u.l2.Bs[g][l2_lb_k+0][l2_lb_j] = make_float2(bv.x, bv.x);
                sm->u.l2.Bs[g][l2_lb_k+1][l2_lb_j] = make_float2(bv.y, bv.y);
                sm->u.l2.Bs[g][l2_lb_k+2][l2_lb_j] = make_float2(bv.z, bv.z);
                sm->u.l2.Bs[g][l2_lb_k+3][l2_lb_j] = make_float2(bv.w, bv.w);
                __syncthreads();
                if (it < 9) {
                    av = __ldcg((const float4*)ap(it+1));
                    bv = *(const float4*)bp(it+1);
                }
                #pragma unroll
                for (int k = 0; k < 32; k++) {
                    ull a  = *(const ull*)&sm->u.l2.As[g][k][2*l2_tn];
                    ull b0 = *(const ull*)&sm->u.l2.Bs[g][k][l2_j0];
                    ull b1 = *(const ull*)&sm->u.l2.Bs[g][k][l2_j0+1];
                    ffma2(a0acc, a, b0);
                    ffma2(a1acc, a, b1);
                }
            }
            __syncthreads();
            { float2 v;
              v=unpack2(a0acc); sm->u.l2.gt[g][l2_j0  ][2*l2_tn]=v.x; sm->u.l2.gt[g][l2_j0  ][2*l2_tn+1]=v.y;
              v=unpack2(a1acc); sm->u.l2.gt[g][l2_j0+1][2*l2_tn]=v.x; sm->u.l2.gt[g][l2_j0+1][2*l2_tn+1]=v.y; }
            __syncthreads();
            if (tid < 256) {
                int nl = tid >> 3, mi = tid & 7;
                int gn = l2_n0 + nl, gm = l2_m0 + mi;
                int ri = gm, rf = KSZ+gm, rg = 2*KSZ+gm, ro = 3*KSZ+gm;
                float gi = sm->u.l2.gt[0][mi   ][nl] + sm->u.l2.gt[1][mi   ][nl] + bih2[ri] + bhh2[ri];
                float gf = sm->u.l2.gt[0][8+mi ][nl] + sm->u.l2.gt[1][8+mi ][nl] + bih2[rf] + bhh2[rf];
                float gg = sm->u.l2.gt[0][16+mi][nl] + sm->u.l2.gt[1][16+mi][nl] + bih2[rg] + bhh2[rg];
                float go = sm->u.l2.gt[0][24+mi][nl] + sm->u.l2.gt[1][24+mi][nl] + bih2[ro] + bhh2[ro];
                float cp = d_c2[gn*KSZ + gm];
                float cn = sigf(gf)*cp + sigf(gi)*tanhf(gg);
                d_c2[gn*KSZ + gm] = cn;
                d_h2[p^1][gn*KSZ + gm] = sigf(go)*tanhf(cn);
            }
        }
        grid_bar();

        // ======== phase 3: attention + output + argmax (block = batch row) ========
        {
            const int n = bid;
            float* ev   = sm->u.at.ev;
            float* h2s  = sm->u.at.h2s;
            float* ctxs = sm->u.at.ctxs;
            float* preds= sm->u.at.preds;
            float* red  = sm->u.at.red;
            float* red2 = sm->u.at.red2;
            if (tid < KSZ) h2s[tid] = __ldcg(&d_h2[p^1][(size_t)n*KSZ + tid]);
            __syncthreads();
            const int L = lens[n];
            const float* krow = key + (size_t)n*KSZ + (size_t)lane*4;
            const float* vrow = val + (size_t)n*VS  + (size_t)lane*4;

            float4 hv = *(const float4*)&h2s[lane*4];
            float wmax = -3.0e38f;
            int tt = wid;
            for (; tt + 48 < L; tt += 64) {
                float4 k0 = *(const float4*)(krow + (size_t)(tt     )*(NB*KSZ));
                float4 k1 = *(const float4*)(krow + (size_t)(tt + 16)*(NB*KSZ));
                float4 k2 = *(const float4*)(krow + (size_t)(tt + 32)*(NB*KSZ));
                float4 k3 = *(const float4*)(krow + (size_t)(tt + 48)*(NB*KSZ));
                float s0 = k0.x*hv.x + k0.y*hv.y + k0.z*hv.z + k0.w*hv.w;
                float s1 = k1.x*hv.x + k1.y*hv.y + k1.z*hv.z + k1.w*hv.w;
                float s2 = k2.x*hv.x + k2.y*hv.y + k2.z*hv.z + k2.w*hv.w;
                float s3 = k3.x*hv.x + k3.y*hv.y + k3.z*hv.z + k3.w*hv.w;
                #pragma unroll
                for (int sh = 16; sh; sh >>= 1) {
                    s0 += __shfl_xor_sync(~0u, s0, sh);
                    s1 += __shfl_xor_sync(~0u, s1, sh);
                    s2 += __shfl_xor_sync(~0u, s2, sh);
                    s3 += __shfl_xor_sync(~0u, s3, sh);
                }
                if (lane == 0) { ev[tt]=s0; ev[tt+16]=s1; ev[tt+32]=s2; ev[tt+48]=s3; }
                wmax = fmaxf(wmax, fmaxf(fmaxf(s0,s1), fmaxf(s2,s3)));
            }
            for (; tt < L; tt += 16) {
                float4 k0 = *(const float4*)(krow + (size_t)tt*(NB*KSZ));
                float s0 = k0.x*hv.x + k0.y*hv.y + k0.z*hv.z + k0.w*hv.w;
                #pragma unroll
                for (int sh = 16; sh; sh >>= 1) s0 += __shfl_xor_sync(~0u, s0, sh);
                if (lane == 0) ev[tt] = s0;
                wmax = fmaxf(wmax, s0);
            }
            if (lane == 0) red[wid] = wmax;
            __syncthreads();
            float m = red[0];
            #pragma unroll
            for (int w = 1; w < 16; w++) m = fmaxf(m, red[w]);

            float psum = 0.f;
            for (int q = tid; q < L; q += 512) { float w = expf(ev[q] - m); ev[q] = w; psum += w; }
            #pragma unroll
            for (int sh = 16; sh; sh >>= 1) psum += __shfl_xor_sync(~0u, psum, sh);
            if (lane == 0) red2[wid] = psum;
            __syncthreads();
            float tot = 0.f;
            #pragma unroll
            for (int w = 0; w < 16; w++) tot += red2[w];
            const float inv = 1.0f / tot;

            float4 a0 = {0,0,0,0}, a1 = {0,0,0,0}, a2 = {0,0,0,0}, a3 = {0,0,0,0};
            tt = wid;
            for (; tt + 48 < L; tt += 64) {
                float e0 = ev[tt], e1 = ev[tt+16], e2 = ev[tt+32], e3 = ev[tt+48];
                float4 v0 = *(const float4*)(vrow + (size_t)(tt     )*(NB*VS));
                float4 v1 = *(const float4*)(vrow + (size_t)(tt + 16)*(NB*VS));
                float4 v2 = *(const float4*)(vrow + (size_t)(tt + 32)*(NB*VS));
                float4 v3 = *(const float4*)(vrow + (size_t)(tt + 48)*(NB*VS));
                a0.x += e0*v0.x; a0.y += e0*v0.y; a0.z += e0*v0.z; a0.w += e0*v0.w;
                a1.x += e1*v1.x; a1.y += e1*v1.y; a1.z += e1*v1.z; a1.w += e1*v1.w;
                a2.x += e2*v2.x; a2.y += e2*v2.y; a2.z += e2*v2.z; a2.w += e2*v2.w;
                a3.x += e3*v3.x; a3.y += e3*v3.y; a3.z += e3*v3.z; a3.w += e3*v3.w;
            }
            for (; tt < L; tt += 16) {
                float e0 = ev[tt];
                float4 v0 = *(const float4*)(vrow + (size_t)tt*(NB*VS));
                a0.x += e0*v0.x; a0.y += e0*v0.y; a0.z += e0*v0.z; a0.w += e0*v0.w;
            }
            a0.x += a1.x + a2.x + a3.x; a0.y += a1.y + a2.y + a3.y;
            a0.z += a1.z + a2.z + a3.z; a0.w += a1.w + a2.w + a3.w;
            *(float4*)&sm->u.at.cpart[wid][lane*4] = a0;
            __syncthreads();
            if (tid < VS) {
                float s = 0.f;
                #pragma unroll
                for (int w = 0; w < 16; w++) s += sm->u.at.cpart[w][tid];
                ctxs[tid] = s * inv;
            }
            __syncthreads();

            for (int v = wid; v < VV; v += 16) {
                const float* wr = Wout + (size_t)v*(KSZ+VS);
                float s = 0.f;
                #pragma unroll
                for (int kk = 0; kk < 8; kk++) {
                    int k = lane + kk*32;
                    float x = (k < KSZ) ? h2s[k] : ctxs[k-KSZ];
                    s += x * wr[k];
                }
                #pragma unroll
                for (int sh = 16; sh; sh >>= 1) s += __shfl_xor_sync(~0u, s, sh);
                if (lane == 0) preds[v] = s + bout[v];
            }
            __syncthreads();
            if (tid < VV) out[(size_t)n*ML*VV + (size_t)step*VV + tid] = preds[tid];
            if (tid == 0) {
                float best = preds[0]; int bi = 0;
                #pragma unroll
                for (int v = 1; v < VV; v++) if (preds[v] > best) { best = preds[v]; bi = v; }
                d_tok[n] = bi;
            }
        }
        grid_bar();
    }
}

extern "C" void kernel_launch(void* const* d_in, const int* in_sizes, int n_in,
                              void* d_out, int out_size) {
    const float* key  = (const float*)d_in[0];
    const float* val  = (const float*)d_in[1];
    const int*   lens = (const int*)  d_in[2];
    const float* emb  = (const float*)d_in[3];
    const float* Wih1 = (const float*)d_in[4];
    const float* Whh1 = (const float*)d_in[5];
    const float* bih1 = (const float*)d_in[6];
    const float* bhh1 = (const float*)d_in[7];
    const float* Wih2 = (const float*)d_in[8];
    const float* Whh2 = (const float*)d_in[9];
    const float* bih2 = (const float*)d_in[10];
    const float* bhh2 = (const float*)d_in[11];
    const float* Wout = (const float*)d_in[12];
    const float* bout = (const float*)d_in[13];
    float* out = (float*)d_out;

    cudaFuncSetAttribute(k_decode, cudaFuncAttributeMaxDynamicSharedMemorySize,
                         (int)sizeof(SMem));

    k_vmean<<<NB, VS>>>(val);
    k_toktab<<<VV, 256>>>(emb, Wih1);
    k_inpc<<<NB, 256>>>(Wih1, bih1, bhh1);
    k_init<<<(NB*HH + 255)/256, 256>>>();
    k_decode<<<NBLK, 512, sizeof(SMem)>>>(key, val, lens, Whh1, Wih2, Whh2,
                                          bih2, bhh2, Wout, bout, out);
}